// round 16
// baseline (speedup 1.0000x reference)
#include <cuda_runtime.h>
#include <cuda_bf16.h>
#include <cstdint>
#include <math.h>

#define TT 4096
#define DD 896

constexpr int NBLK = 32;                     // 128-blocks over T
constexpr int NPAIR = NBLK * (NBLK + 1) / 2; // 528 causal 128x128 pairs
constexpr int NKT_FULL = DD / 32;            // 28
constexpr int NKT2 = NKT_FULL / 2;           // 14 double-ktiles (BK=64)
constexpr int NKT_T = TT / 32;               // 128
constexpr int NDB = DD / 128;                // 7

// fragment slabs (words; 1 word = 2 bf16 = one k-pair)
constexpr int A_SLAB = 2048;                 // 128 rows x 32 k
constexpr int B_SLAB = 2048;                 // 128 cols x 32 k
constexpr int STAGE1 = 2 * (A_SLAB + B_SLAB);   // BK=64 1x stage: 8192 w = 32 KB
constexpr int STAGE3 = 2 * (A_SLAB + B_SLAB);   // g stage (Ah,Al,Bh,Bl): 32 KB
constexpr unsigned DSMEM1 = 3u * STAGE1 * 4u;   // 98304
constexpr unsigned DSMEM3 = 3u * STAGE3 * 4u;   // 98304
constexpr unsigned DSMEM_SM = 16384;            // softmax row buffer

// ---------------- scratch (device globals: allocation-free) ----------------
__device__ float g_h[(size_t)TT * DD];
__device__ float g_g[(size_t)TT * DD];
__device__ float g_part0[(size_t)TT * DD];
__device__ float g_part1[(size_t)TT * DD];
__device__ float g_sim[(size_t)TT * TT];
__device__ float g_hn2[TT];
__device__ float g_maxQ[TT];

// pre-packed bf16 fragment tables
__device__ unsigned T_hA [(size_t)NBLK * NKT_FULL * A_SLAB];  // h, A-layout hi
__device__ unsigned T_hB [(size_t)NBLK * NKT_FULL * B_SLAB];  // h, B n-major hi
__device__ unsigned T_hTh[(size_t)NDB  * NKT_T    * B_SLAB];  // h^T, B k-major hi
__device__ unsigned T_hTl[(size_t)NDB  * NKT_T    * B_SLAB];  // lo
__device__ unsigned T_aAh[(size_t)NBLK * NKT_T    * A_SLAB];  // alpha, A-layout hi
__device__ unsigned T_aAl[(size_t)NBLK * NKT_T    * A_SLAB];  // lo
__device__ unsigned T_gA [(size_t)NBLK * NKT_FULL * A_SLAB];  // g, A-layout hi

// ---------------- small helpers ----------------
__device__ __forceinline__ unsigned pk(float lo, float hi) {
    unsigned r;
    asm("cvt.rn.bf16x2.f32 %0, %1, %2;" : "=r"(r) : "f"(hi), "f"(lo));
    return r;
}
__device__ __forceinline__ void bsplit(float x, float& h, float& l) {
    h = __bfloat162float(__float2bfloat16(x));
    l = x - h;
}
__device__ __forceinline__ void mma16(float* d, const unsigned* a, const unsigned* b) {
    asm volatile(
        "mma.sync.aligned.m16n8k16.row.col.f32.bf16.bf16.f32 "
        "{%0,%1,%2,%3}, {%4,%5,%6,%7}, {%8,%9}, {%0,%1,%2,%3};\n"
        : "+f"(d[0]), "+f"(d[1]), "+f"(d[2]), "+f"(d[3])
        : "r"(a[0]), "r"(a[1]), "r"(a[2]), "r"(a[3]),
          "r"(b[0]), "r"(b[1]));
}
__device__ __forceinline__ uint32_t smem_to_u32(const void* p) {
    uint32_t a;
    asm("{ .reg .u64 t; cvta.to.shared.u64 t, %1; cvt.u32.u64 %0, t; }" : "=r"(a) : "l"(p));
    return a;
}
__device__ __forceinline__ void cpa16(uint32_t s, const void* g) {
    asm volatile("cp.async.cg.shared.global [%0], [%1], 16;" :: "r"(s), "l"(g) : "memory");
}
#define CP_COMMIT() asm volatile("cp.async.commit_group;" ::: "memory")
#define CP_WAIT1()  asm volatile("cp.async.wait_group 1;" ::: "memory")

// fragment word index within an A slab (m in 0..127, kp in 0..15)
__device__ __forceinline__ int wordA(int m, int kp) {
    int grp = (m >> 4) * 2 + (kp >> 3);
    int lane = (m & 7) * 4 + (kp & 3);
    int j = (((kp & 7) >= 4) ? 2 : 0) + (((m & 15) >= 8) ? 1 : 0);
    return grp * 128 + lane * 4 + j;
}
// fragment word index within a B slab (n in 0..127, kp in 0..15)
__device__ __forceinline__ int wordB(int n, int kp) {
    int grp = (n >> 3) * 2 + (kp >> 3);
    int lane = (n & 7) * 4 + (kp & 3);
    int j = ((kp & 7) >= 4) ? 1 : 0;
    return grp * 64 + lane * 2 + j;
}
__device__ __forceinline__ float blockReduceSum(float v, float* sh) {
    int lane = threadIdx.x & 31, w = threadIdx.x >> 5;
#pragma unroll
    for (int o = 16; o; o >>= 1) v += __shfl_xor_sync(0xffffffffu, v, o);
    __syncthreads();
    if (lane == 0) sh[w] = v;
    __syncthreads();
    if (threadIdx.x == 0) {
        float s = 0.f;
        int nw = (blockDim.x + 31) >> 5;
        for (int i = 0; i < nw; i++) s += sh[i];
        sh[0] = s;
    }
    __syncthreads();
    return sh[0];
}
__device__ __forceinline__ float blockReduceMax(float v, float* sh) {
    int lane = threadIdx.x & 31, w = threadIdx.x >> 5;
#pragma unroll
    for (int o = 16; o; o >>= 1) v = fmaxf(v, __shfl_xor_sync(0xffffffffu, v, o));
    __syncthreads();
    if (lane == 0) sh[w] = v;
    __syncthreads();
    if (threadIdx.x == 0) {
        float m = -3.0e38f;
        int nw = (blockDim.x + 31) >> 5;
        for (int i = 0; i < nw; i++) m = fmaxf(m, sh[i]);
        sh[0] = m;
    }
    __syncthreads();
    return sh[0];
}
__device__ __forceinline__ void atomicMaxF(float* addr, float val) {
    int old = __float_as_int(*addr);
    while (__int_as_float(old) < val) {
        int assumed = old;
        old = atomicCAS((int*)addr, assumed, __float_as_int(val));
        if (old == assumed) break;
    }
}
__device__ __forceinline__ void triDecode(int b, int& ib, int& jb) {
    int i = (int)floorf((sqrtf(8.0f * (float)b + 1.0f) - 1.0f) * 0.5f);
    while ((i + 1) * (i + 2) / 2 <= b) i++;
    while (i * (i + 1) / 2 > b) i--;
    ib = i;
    jb = b - i * (i + 1) / 2;
}

// ---------------- MMA bodies ----------------
// 1x: plain hi*hi
__device__ __forceinline__ void mma_part1(const unsigned* A, const unsigned* B,
                                          float acc[4][4][4], int wm, int wn, int lane) {
#pragma unroll
    for (int ksg = 0; ksg < 2; ksg++) {
        unsigned bh[4][2];
#pragma unroll
        for (int j = 0; j < 4; j++) {
            int off = ((wn * 4 + j) * 2 + ksg) * 64 + lane * 2;
            *(uint2*)bh[j] = *(const uint2*)&B[off];
        }
#pragma unroll
        for (int i = 0; i < 4; i++) {
            int offA = ((wm * 4 + i) * 2 + ksg) * 128 + lane * 4;
            unsigned ah[4];
            *(uint4*)ah = *(const uint4*)&A[offA];
#pragma unroll
            for (int j = 0; j < 4; j++) mma16(acc[i][j], ah, bh[j]);
        }
    }
}
// 3x: ah*bl + al*bh + ah*bh (full compensation; Al = A+A_SLAB, Bl = B+B_SLAB)
__device__ __forceinline__ void mma_part3(const unsigned* A, const unsigned* B,
                                          float acc[4][4][4], int wm, int wn, int lane) {
    const unsigned* Al = A + A_SLAB;
    const unsigned* Bl = B + B_SLAB;
#pragma unroll
    for (int ksg = 0; ksg < 2; ksg++) {
        unsigned bh[4][2], bl[4][2];
#pragma unroll
        for (int j = 0; j < 4; j++) {
            int off = ((wn * 4 + j) * 2 + ksg) * 64 + lane * 2;
            *(uint2*)bh[j] = *(const uint2*)&B[off];
            *(uint2*)bl[j] = *(const uint2*)&Bl[off];
        }
#pragma unroll
        for (int i = 0; i < 4; i++) {
            int offA = ((wm * 4 + i) * 2 + ksg) * 128 + lane * 4;
            unsigned ah[4], al[4];
            *(uint4*)ah = *(const uint4*)&A[offA];
            *(uint4*)al = *(const uint4*)&Al[offA];
#pragma unroll
            for (int j = 0; j < 4; j++) {
                mma16(acc[i][j], ah, bl[j]);
                mma16(acc[i][j], al, bh[j]);
                mma16(acc[i][j], ah, bh[j]);
            }
        }
    }
}

#define ACC_INIT(acc)                      \
    _Pragma("unroll")                      \
    for (int i = 0; i < 4; i++)            \
    _Pragma("unroll")                      \
    for (int j = 0; j < 4; j++)            \
    _Pragma("unroll")                      \
    for (int e = 0; e < 4; e++) acc[i][j][e] = 0.f;

// ---------------- kernel 1: normalize + pack h (A, Bn, BT hi/lo) -----------
__global__ void k_normalize(const float* __restrict__ x) {
    __shared__ float sh[32];
    int t = blockIdx.x;
    const float* row = x + (size_t)t * DD;
    float ss = 0.f;
    for (int i = threadIdx.x; i < DD; i += blockDim.x) {
        float v = row[i];
        ss += v * v;
    }
    ss = blockReduceSum(ss, sh);
    float inv = 1.0f / fmaxf(sqrtf(ss), 1e-12f);
    float* hr = g_h + (size_t)t * DD;
    int mA = t & 127;
    size_t baseA = ((size_t)(t >> 7) * NKT_FULL) * A_SLAB;
    size_t baseB = ((size_t)(t >> 7) * NKT_FULL) * B_SLAB;
    for (int dp = threadIdx.x; dp < DD / 2; dp += blockDim.x) {
        int d = dp * 2;
        float v0 = row[d] * inv, v1 = row[d + 1] * inv;
        hr[d] = v0;
        hr[d + 1] = v1;
        int kt = dp >> 4, kpl = dp & 15;
        unsigned w = pk(v0, v1);
        T_hA[baseA + (size_t)kt * A_SLAB + wordA(mA, kpl)] = w;
        T_hB[baseB + (size_t)kt * B_SLAB + wordB(mA, kpl)] = w;
    }
    // h^T table (B k-major): element (t, d) -> slab (d>>7, t>>5),
    // word wordB(d&127, (t&31)>>1), bf16 half index t&1 (pk packs even-t low).
    {
        __nv_bfloat16* Th = (__nv_bfloat16*)T_hTh;
        __nv_bfloat16* Tl = (__nv_bfloat16*)T_hTl;
        size_t ktb = (size_t)(t >> 5);
        int kp = (t & 31) >> 1, half = t & 1;
        for (int d = threadIdx.x; d < DD; d += blockDim.x) {
            float v = row[d] * inv;
            float hh, ll;
            bsplit(v, hh, ll);
            size_t e = (((size_t)(d >> 7) * NKT_T + ktb) * B_SLAB +
                        wordB(d & 127, kp)) * 2 + half;
            Th[e] = __float2bfloat16(hh);
            Tl[e] = __float2bfloat16(ll);
        }
    }
    if (threadIdx.x == 0) {
        g_hn2[t] = ss * inv * inv;
        g_maxQ[t] = -3.0e38f;
    }
}

// ---------------- kernel 2: sim = h h^T (1xBF16, BK=64, cp.async ring) -----
__global__ void __launch_bounds__(256, 2) k_sim() {
    extern __shared__ unsigned dsm[];
    uint32_t sb = smem_to_u32(dsm);
    int tid = threadIdx.x, lane = tid & 31, warp = tid >> 5;
    int wm = warp >> 2, wn = warp & 3, gr = lane >> 2, gc = lane & 3;
    int ib, jb;
    triDecode(blockIdx.x, ib, jb);
    int rowA = ib * 128, rowB = jb * 128;

    float acc[4][4][4];
    ACC_INIT(acc)

    const uint4* A4 = (const uint4*)(T_hA + ((size_t)ib * NKT_FULL) * A_SLAB);
    const uint4* B4 = (const uint4*)(T_hB + ((size_t)jb * NKT_FULL) * B_SLAB);

    auto issue = [&](int k2, int buf) {
        uint32_t s = sb + (unsigned)buf * (STAGE1 * 4);
        const uint4* As = A4 + (size_t)k2 * 1024;
        const uint4* Bs = B4 + (size_t)k2 * 1024;
#pragma unroll
        for (int it = 0; it < 4; it++) {
            cpa16(s + (tid + it * 256) * 16, As + tid + it * 256);
            cpa16(s + 16384 + (tid + it * 256) * 16, Bs + tid + it * 256);
        }
    };

    issue(0, 0); CP_COMMIT();
    issue(1, 1); CP_COMMIT();

    for (int k2 = 0; k2 < NKT2; k2++) {
        CP_WAIT1();
        __syncthreads();
        if (k2 + 2 < NKT2) issue(k2 + 2, (k2 + 2) % 3);
        CP_COMMIT();
        const unsigned* S = dsm + (k2 % 3) * STAGE1;
        mma_part1(S, S + 4096, acc, wm, wn, lane);
        mma_part1(S + 2048, S + 6144, acc, wm, wn, lane);
    }

#pragma unroll
    for (int i = 0; i < 4; i++) {
        int t = rowA + (wm * 4 + i) * 16 + gr;
#pragma unroll
        for (int j = 0; j < 4; j++) {
            int s = rowB + (wn * 4 + j) * 8 + gc * 2;
            *(float2*)&g_sim[(size_t)t * TT + s]       = make_float2(acc[i][j][0], acc[i][j][1]);
            *(float2*)&g_sim[(size_t)(t + 8) * TT + s] = make_float2(acc[i][j][2], acc[i][j][3]);
        }
    }
}

// ---------------- kernel 3: softmax (smem row) -> packed alpha fragments ---
__global__ void k_softmax() {
    extern __shared__ float srow[];
    __shared__ float sh[32];
    int t = blockIdx.x;
    const float* row = g_sim + (size_t)t * TT;
    int n = t + 1;
    const float sqrt_d = sqrtf((float)DD);
    float lmax = -3.0e38f;
    for (int s = threadIdx.x; s < n; s += blockDim.x) {
        float tds = (float)(t - s);
        float l = row[s] / (sqrt_d * expf(0.1f * tds) + 1e-8f) * 1.0f;
        // identical formula to the old precomputed table: 1/(sqrt_d*e^{0.1Δ}+1e-8)
        l = row[s] * (1.0f / (sqrt_d * expf(0.1f * tds) + 1e-8f));
        srow[s] = l;
        lmax = fmaxf(lmax, l);
    }
    lmax = blockReduceMax(lmax, sh);
    float lsum = 0.f;
    for (int s = threadIdx.x; s < n; s += blockDim.x) {
        float e = __expf(srow[s] - lmax);
        srow[s] = e;
        lsum += e;
    }
    lsum = blockReduceSum(lsum, sh);
    float inv = 1.0f / lsum;

    int ib = t >> 7, m = t & 127;
    size_t base = ((size_t)ib * NKT_T) * A_SLAB;
    int npairs = (ib + 1) * 64;
    for (int sp = threadIdx.x; sp < npairs; sp += blockDim.x) {
        int s0 = 2 * sp, s1 = s0 + 1;
        float v0 = (s0 <= t) ? srow[s0] * inv : 0.f;
        float v1 = (s1 <= t) ? srow[s1] * inv : 0.f;
        float h0, l0, h1, l1;
        bsplit(v0, h0, l0);
        bsplit(v1, h1, l1);
        size_t idx = base + (size_t)(sp >> 4) * A_SLAB + wordA(m, sp & 15);
        T_aAh[idx] = pk(h0, h1);
        T_aAl[idx] = pk(l0, l1);
    }
}

// ---------------- kernel 4: g = alpha @ h (3xBF16, split-K=2) --------------
__global__ void __launch_bounds__(256, 2) k_g() {
    extern __shared__ unsigned dsm[];
    uint32_t sb = smem_to_u32(dsm);
    int tid = threadIdx.x, lane = tid & 31, warp = tid >> 5;
    int wm = warp >> 2, wn = warp & 3, gr = lane >> 2, gc = lane & 3;
    int jbD = blockIdx.x;
    int ib = (NBLK - 1) - blockIdx.y;     // long blocks first
    int z = blockIdx.z;                   // k-split half
    int rowA = ib * 128, colB = jbD * 128;
    int nkt = (ib + 1) * 4;
    int beg = z ? nkt / 2 : 0;
    int end = z ? nkt : nkt / 2;

    float acc[4][4][4];
    ACC_INIT(acc)

    const uint4* Ah4 = (const uint4*)(T_aAh + ((size_t)ib * NKT_T) * A_SLAB);
    const uint4* Al4 = (const uint4*)(T_aAl + ((size_t)ib * NKT_T) * A_SLAB);
    const uint4* Bh4 = (const uint4*)(T_hTh + ((size_t)jbD * NKT_T) * B_SLAB);
    const uint4* Bl4 = (const uint4*)(T_hTl + ((size_t)jbD * NKT_T) * B_SLAB);

    // stage layout: [Ah(2048) Al(2048) Bh(2048) Bl(2048)] words
    auto issue = [&](int kt, int buf) {
        uint32_t s = sb + (unsigned)buf * (STAGE3 * 4);
        size_t o = (size_t)kt * 512;
#pragma unroll
        for (int it = 0; it < 2; it++) {
            cpa16(s + (tid + it * 256) * 16, Ah4 + o + tid + it * 256);
            cpa16(s + 8192 + (tid + it * 256) * 16, Al4 + o + tid + it * 256);
            cpa16(s + 16384 + (tid + it * 256) * 16, Bh4 + o + tid + it * 256);
            cpa16(s + 24576 + (tid + it * 256) * 16, Bl4 + o + tid + it * 256);
        }
    };

    issue(beg, 0); CP_COMMIT();
    issue(beg + 1, 1); CP_COMMIT();       // end-beg >= 2 always

    int cnt = end - beg;
    for (int i = 0; i < cnt; i++) {
        CP_WAIT1();
        __syncthreads();
        if (i + 2 < cnt) issue(beg + i + 2, (i + 2) % 3);
        CP_COMMIT();
        const unsigned* S = dsm + (i % 3) * STAGE3;
        mma_part3(S, S + 4096, acc, wm, wn, lane);
    }

    float* dst = z ? g_part1 : g_part0;
#pragma unroll
    for (int i = 0; i < 4; i++) {
#pragma unroll
        for (int half = 0; half < 2; half++) {
            int t = rowA + (wm * 4 + i) * 16 + gr + half * 8;
#pragma unroll
            for (int j = 0; j < 4; j++) {
                int d = colB + (wn * 4 + j) * 8 + gc * 2;
                *(float2*)&dst[(size_t)t * DD + d] =
                    make_float2(acc[i][j][half * 2], acc[i][j][half * 2 + 1]);
            }
        }
    }
}

// ---------------- kernel 4b: g = part0 + part1; write fp32 + packed frags --
__global__ void k_gred() {
    int t = blockIdx.x;
    int m = t & 127;
    size_t roff = (size_t)t * DD;
    size_t gbase = ((size_t)(t >> 7) * NKT_FULL) * A_SLAB;
    for (int dp = threadIdx.x; dp < DD / 2; dp += blockDim.x) {
        int d = dp * 2;
        float2 a = *(const float2*)&g_part0[roff + d];
        float2 b = *(const float2*)&g_part1[roff + d];
        float v0 = a.x + b.x, v1 = a.y + b.y;
        *(float2*)&g_g[roff + d] = make_float2(v0, v1);
        T_gA[gbase + (size_t)(dp >> 4) * A_SLAB + wordA(m, dp & 15)] = pk(v0, v1);
    }
}

// ---------------- kernel 5: cross = g h^T + fused causal max (1xBF16) ------
__global__ void __launch_bounds__(256, 2) k_cross() {
    extern __shared__ unsigned dsm[];
    uint32_t sb = smem_to_u32(dsm);
    int tid = threadIdx.x, lane = tid & 31, warp = tid >> 5;
    int wm = warp >> 2, wn = warp & 3, gr = lane >> 2, gc = lane & 3;
    int ib, jb;
    triDecode(blockIdx.x, ib, jb);
    int rowA = ib * 128, rowB = jb * 128;

    float acc[4][4][4];
    ACC_INIT(acc)

    const uint4* A4 = (const uint4*)(T_gA + ((size_t)ib * NKT_FULL) * A_SLAB);
    const uint4* B4 = (const uint4*)(T_hB + ((size_t)jb * NKT_FULL) * B_SLAB);

    auto issue = [&](int k2, int buf) {
        uint32_t s = sb + (unsigned)buf * (STAGE1 * 4);
        const uint4* As = A4 + (size_t)k2 * 1024;
        const uint4* Bs = B4 + (size_t)k2 * 1024;
#pragma unroll
        for (int it = 0; it < 4; it++) {
            cpa16(s + (tid + it * 256) * 16, As + tid + it * 256);
            cpa16(s + 16384 + (tid + it * 256) * 16, Bs + tid + it * 256);
        }
    };

    issue(0, 0); CP_COMMIT();
    issue(1, 1); CP_COMMIT();

    for (int k2 = 0; k2 < NKT2; k2++) {
        CP_WAIT1();
        __syncthreads();
        if (k2 + 2 < NKT2) issue(k2 + 2, (k2 + 2) % 3);
        CP_COMMIT();
        const unsigned* S = dsm + (k2 % 3) * STAGE1;
        mma_part1(S, S + 4096, acc, wm, wn, lane);
        mma_part1(S + 2048, S + 6144, acc, wm, wn, lane);
    }

    // epilogue: maxQ[t] = max_{s<=t}(hn2[s] - 2*cross[t,s])
    float hn[4][2];
#pragma unroll
    for (int j = 0; j < 4; j++)
#pragma unroll
        for (int e = 0; e < 2; e++)
            hn[j][e] = g_hn2[rowB + (wn * 4 + j) * 8 + gc * 2 + e];

    __syncthreads();
    float* red = (float*)dsm;
#pragma unroll
    for (int i = 0; i < 4; i++) {
        int rloc = (wm * 4 + i) * 16 + gr;
        int t0 = rowA + rloc;
        float m0 = -3.0e38f, m1 = -3.0e38f;
#pragma unroll
        for (int j = 0; j < 4; j++)
#pragma unroll
            for (int e = 0; e < 2; e++) {
                int s = rowB + (wn * 4 + j) * 8 + gc * 2 + e;
                float q0 = hn[j][e] - 2.0f * acc[i][j][e];
                float q1 = hn[j][e] - 2.0f * acc[i][j][2 + e];
                if (s <= t0)     m0 = fmaxf(m0, q0);
                if (s <= t0 + 8) m1 = fmaxf(m1, q1);
            }
#pragma unroll
        for (int o = 1; o < 4; o <<= 1) {
            m0 = fmaxf(m0, __shfl_xor_sync(0xffffffffu, m0, o));
            m1 = fmaxf(m1, __shfl_xor_sync(0xffffffffu, m1, o));
        }
        if (gc == 0) {
            red[rloc * 4 + wn]       = m0;
            red[(rloc + 8) * 4 + wn] = m1;
        }
    }
    __syncthreads();
    if (tid < 128) {
        float m = fmaxf(fmaxf(red[tid * 4], red[tid * 4 + 1]),
                        fmaxf(red[tid * 4 + 2], red[tid * 4 + 3]));
        if (m > -2.0e38f) atomicMaxF(&g_maxQ[rowA + tid], m);
    }
}

// ---------------- kernel 6: final elementwise ------------------------------
__global__ void k_final(const float* __restrict__ m_t, const float* __restrict__ c_t,
                        const float* __restrict__ d_t, const float* __restrict__ mu,
                        float* __restrict__ out) {
    __shared__ float sh[32];
    int t = blockIdx.x;
    const float* hr = g_h + (size_t)t * DD;
    const float* gr = g_g + (size_t)t * DD;
    float dd = 0.f, gn2 = 0.f;
    for (int i = threadIdx.x; i < DD; i += blockDim.x) {
        float hv = hr[i], gv = gr[i];
        float df = hv - gv;
        dd += df * df;
        gn2 += gv * gv;
    }
    dd = blockReduceSum(dd, sh);
    gn2 = blockReduceSum(gn2, sh);
    if (threadIdx.x == 0) {
        float dist = sqrtf(fmaxf(dd, 1e-24f));
        float dmax = sqrtf(fmaxf(gn2 + g_maxQ[t], 1e-24f));
        if (dmax < 1e-6f) dmax = 1.0f;
        float ratio = dist / (dmax + 1e-8f);
        float stab = 1.0f - 0.3f * c_t[t] + 0.2f * d_t[t];
        float xi = 1.0f - mu[0] * m_t[t];
        float v = ratio * stab * xi;
        out[t] = fminf(fmaxf(v, 0.0f), 1.0f);
    }
}

// ---------------- launch ----------------------------------------------------
extern "C" void kernel_launch(void* const* d_in, const int* in_sizes, int n_in,
                              void* d_out, int out_size) {
    const float* x   = (const float*)d_in[0];
    const float* m_t = (const float*)d_in[1];
    const float* c_t = (const float*)d_in[2];
    const float* d_t = (const float*)d_in[3];
    const float* mu  = (const float*)d_in[4];
    float* out = (float*)d_out;

    cudaFuncSetAttribute(k_sim,     cudaFuncAttributeMaxDynamicSharedMemorySize, DSMEM1);
    cudaFuncSetAttribute(k_g,       cudaFuncAttributeMaxDynamicSharedMemorySize, DSMEM3);
    cudaFuncSetAttribute(k_cross,   cudaFuncAttributeMaxDynamicSharedMemorySize, DSMEM1);
    cudaFuncSetAttribute(k_softmax, cudaFuncAttributeMaxDynamicSharedMemorySize, DSMEM_SM);

    k_normalize<<<TT, 256>>>(x);
    k_sim<<<NPAIR, 256, DSMEM1>>>();
    k_softmax<<<TT, 256, DSMEM_SM>>>();
    k_g<<<dim3(NDB, NBLK, 2), 256, DSMEM3>>>();
    k_gred<<<TT, 256>>>();
    k_cross<<<NPAIR, 256, DSMEM1>>>();
    k_final<<<TT, 256>>>(m_t, c_t, d_t, mu, out);
}

// round 17
// speedup vs baseline: 1.1019x; 1.1019x over previous
#include <cuda_runtime.h>
#include <cuda_bf16.h>
#include <cstdint>
#include <math.h>

#define TT 4096
#define DD 896

constexpr int NBLK = 32;                     // 128-blocks over T
constexpr int NPAIR = NBLK * (NBLK + 1) / 2; // 528 causal 128x128 pairs
constexpr int NKT_FULL = DD / 32;            // 28
constexpr int NKT2 = NKT_FULL / 2;           // 14 double-ktiles (BK=64)
constexpr int NKT_T = TT / 32;               // 128
constexpr int NDB = DD / 128;                // 7

// fragment slabs (words; 1 word = 2 bf16 = one k-pair)
constexpr int A_SLAB = 2048;                 // 128 rows x 32 k
constexpr int B_SLAB = 2048;                 // 128 cols x 32 k
constexpr int STAGE1 = 2 * (A_SLAB + B_SLAB);   // BK=64 1x stage: 8192 w = 32 KB
constexpr int STAGE3 = 2 * (A_SLAB + B_SLAB);   // g stage (Ah,Al,Bh,Bl): 32 KB
constexpr unsigned DSMEM1 = 3u * STAGE1 * 4u;   // 98304
constexpr unsigned DSMEM3 = 3u * STAGE3 * 4u;   // 98304
constexpr unsigned DSMEM_SM = 16384;            // softmax row buffer

// ---------------- scratch (device globals: allocation-free) ----------------
__device__ float g_h[(size_t)TT * DD];
__device__ float g_g[(size_t)TT * DD];
__device__ float g_part0[(size_t)TT * DD];
__device__ float g_part1[(size_t)TT * DD];
__device__ float g_sim[(size_t)TT * TT];
__device__ float g_hn2[TT];
__device__ float g_maxQ[TT];
__device__ float g_invden[TT];

// pre-packed bf16 fragment tables
__device__ unsigned T_hA [(size_t)NBLK * NKT_FULL * A_SLAB];  // h, A-layout hi
__device__ unsigned T_hB [(size_t)NBLK * NKT_FULL * B_SLAB];  // h, B n-major hi
__device__ unsigned T_hTh[(size_t)NDB  * NKT_T    * B_SLAB];  // h^T, B k-major hi
__device__ unsigned T_hTl[(size_t)NDB  * NKT_T    * B_SLAB];  // lo
__device__ unsigned T_aAh[(size_t)NBLK * NKT_T    * A_SLAB];  // alpha, A-layout hi
__device__ unsigned T_aAl[(size_t)NBLK * NKT_T    * A_SLAB];  // lo
__device__ unsigned T_gA [(size_t)NBLK * NKT_FULL * A_SLAB];  // g, A-layout hi

// ---------------- small helpers ----------------
__device__ __forceinline__ unsigned pk(float lo, float hi) {
    unsigned r;
    asm("cvt.rn.bf16x2.f32 %0, %1, %2;" : "=r"(r) : "f"(hi), "f"(lo));
    return r;
}
__device__ __forceinline__ void bsplit(float x, float& h, float& l) {
    h = __bfloat162float(__float2bfloat16(x));
    l = x - h;
}
__device__ __forceinline__ void mma16(float* d, const unsigned* a, const unsigned* b) {
    asm volatile(
        "mma.sync.aligned.m16n8k16.row.col.f32.bf16.bf16.f32 "
        "{%0,%1,%2,%3}, {%4,%5,%6,%7}, {%8,%9}, {%0,%1,%2,%3};\n"
        : "+f"(d[0]), "+f"(d[1]), "+f"(d[2]), "+f"(d[3])
        : "r"(a[0]), "r"(a[1]), "r"(a[2]), "r"(a[3]),
          "r"(b[0]), "r"(b[1]));
}
__device__ __forceinline__ uint32_t smem_to_u32(const void* p) {
    uint32_t a;
    asm("{ .reg .u64 t; cvta.to.shared.u64 t, %1; cvt.u32.u64 %0, t; }" : "=r"(a) : "l"(p));
    return a;
}
__device__ __forceinline__ void cpa16(uint32_t s, const void* g) {
    asm volatile("cp.async.cg.shared.global [%0], [%1], 16;" :: "r"(s), "l"(g) : "memory");
}
#define CP_COMMIT() asm volatile("cp.async.commit_group;" ::: "memory")
#define CP_WAIT1()  asm volatile("cp.async.wait_group 1;" ::: "memory")

// fragment word index within an A slab (m in 0..127, kp in 0..15)
__device__ __forceinline__ int wordA(int m, int kp) {
    int grp = (m >> 4) * 2 + (kp >> 3);
    int lane = (m & 7) * 4 + (kp & 3);
    int j = (((kp & 7) >= 4) ? 2 : 0) + (((m & 15) >= 8) ? 1 : 0);
    return grp * 128 + lane * 4 + j;
}
// fragment word index within a B slab (n in 0..127, kp in 0..15)
__device__ __forceinline__ int wordB(int n, int kp) {
    int grp = (n >> 3) * 2 + (kp >> 3);
    int lane = (n & 7) * 4 + (kp & 3);
    int j = ((kp & 7) >= 4) ? 1 : 0;
    return grp * 64 + lane * 2 + j;
}
__device__ __forceinline__ float blockReduceSum(float v, float* sh) {
    int lane = threadIdx.x & 31, w = threadIdx.x >> 5;
#pragma unroll
    for (int o = 16; o; o >>= 1) v += __shfl_xor_sync(0xffffffffu, v, o);
    __syncthreads();
    if (lane == 0) sh[w] = v;
    __syncthreads();
    if (threadIdx.x == 0) {
        float s = 0.f;
        int nw = (blockDim.x + 31) >> 5;
        for (int i = 0; i < nw; i++) s += sh[i];
        sh[0] = s;
    }
    __syncthreads();
    return sh[0];
}
__device__ __forceinline__ float blockReduceMax(float v, float* sh) {
    int lane = threadIdx.x & 31, w = threadIdx.x >> 5;
#pragma unroll
    for (int o = 16; o; o >>= 1) v = fmaxf(v, __shfl_xor_sync(0xffffffffu, v, o));
    __syncthreads();
    if (lane == 0) sh[w] = v;
    __syncthreads();
    if (threadIdx.x == 0) {
        float m = -3.0e38f;
        int nw = (blockDim.x + 31) >> 5;
        for (int i = 0; i < nw; i++) m = fmaxf(m, sh[i]);
        sh[0] = m;
    }
    __syncthreads();
    return sh[0];
}
__device__ __forceinline__ void atomicMaxF(float* addr, float val) {
    int old = __float_as_int(*addr);
    while (__int_as_float(old) < val) {
        int assumed = old;
        old = atomicCAS((int*)addr, assumed, __float_as_int(val));
        if (old == assumed) break;
    }
}
__device__ __forceinline__ void triDecode(int b, int& ib, int& jb) {
    int i = (int)floorf((sqrtf(8.0f * (float)b + 1.0f) - 1.0f) * 0.5f);
    while ((i + 1) * (i + 2) / 2 <= b) i++;
    while (i * (i + 1) / 2 > b) i--;
    ib = i;
    jb = b - i * (i + 1) / 2;
}

// ---------------- MMA bodies ----------------
// 1x: plain hi*hi
__device__ __forceinline__ void mma_part1(const unsigned* A, const unsigned* B,
                                          float acc[4][4][4], int wm, int wn, int lane) {
#pragma unroll
    for (int ksg = 0; ksg < 2; ksg++) {
        unsigned bh[4][2];
#pragma unroll
        for (int j = 0; j < 4; j++) {
            int off = ((wn * 4 + j) * 2 + ksg) * 64 + lane * 2;
            *(uint2*)bh[j] = *(const uint2*)&B[off];
        }
#pragma unroll
        for (int i = 0; i < 4; i++) {
            int offA = ((wm * 4 + i) * 2 + ksg) * 128 + lane * 4;
            unsigned ah[4];
            *(uint4*)ah = *(const uint4*)&A[offA];
#pragma unroll
            for (int j = 0; j < 4; j++) mma16(acc[i][j], ah, bh[j]);
        }
    }
}
// 3x: ah*bl + al*bh + ah*bh (full compensation; Al = A+A_SLAB, Bl = B+B_SLAB)
__device__ __forceinline__ void mma_part3(const unsigned* A, const unsigned* B,
                                          float acc[4][4][4], int wm, int wn, int lane) {
    const unsigned* Al = A + A_SLAB;
    const unsigned* Bl = B + B_SLAB;
#pragma unroll
    for (int ksg = 0; ksg < 2; ksg++) {
        unsigned bh[4][2], bl[4][2];
#pragma unroll
        for (int j = 0; j < 4; j++) {
            int off = ((wn * 4 + j) * 2 + ksg) * 64 + lane * 2;
            *(uint2*)bh[j] = *(const uint2*)&B[off];
            *(uint2*)bl[j] = *(const uint2*)&Bl[off];
        }
#pragma unroll
        for (int i = 0; i < 4; i++) {
            int offA = ((wm * 4 + i) * 2 + ksg) * 128 + lane * 4;
            unsigned ah[4], al[4];
            *(uint4*)ah = *(const uint4*)&A[offA];
            *(uint4*)al = *(const uint4*)&Al[offA];
#pragma unroll
            for (int j = 0; j < 4; j++) {
                mma16(acc[i][j], ah, bl[j]);
                mma16(acc[i][j], al, bh[j]);
                mma16(acc[i][j], ah, bh[j]);
            }
        }
    }
}

#define ACC_INIT(acc)                      \
    _Pragma("unroll")                      \
    for (int i = 0; i < 4; i++)            \
    _Pragma("unroll")                      \
    for (int j = 0; j < 4; j++)            \
    _Pragma("unroll")                      \
    for (int e = 0; e < 4; e++) acc[i][j][e] = 0.f;

// ---------------- kernel 1: normalize + pack h (A-layout, B n-major) -------
__global__ void k_normalize(const float* __restrict__ x) {
    __shared__ float sh[32];
    int t = blockIdx.x;
    const float* row = x + (size_t)t * DD;
    float ss = 0.f;
    for (int i = threadIdx.x; i < DD; i += blockDim.x) {
        float v = row[i];
        ss += v * v;
    }
    ss = blockReduceSum(ss, sh);
    float inv = 1.0f / fmaxf(sqrtf(ss), 1e-12f);
    float* hr = g_h + (size_t)t * DD;
    int mA = t & 127;
    size_t baseA = ((size_t)(t >> 7) * NKT_FULL) * A_SLAB;
    size_t baseB = ((size_t)(t >> 7) * NKT_FULL) * B_SLAB;
    for (int dp = threadIdx.x; dp < DD / 2; dp += blockDim.x) {
        int d = dp * 2;
        float v0 = row[d] * inv, v1 = row[d + 1] * inv;
        hr[d] = v0;
        hr[d + 1] = v1;
        int kt = dp >> 4, kpl = dp & 15;
        unsigned w = pk(v0, v1);
        T_hA[baseA + (size_t)kt * A_SLAB + wordA(mA, kpl)] = w;
        T_hB[baseB + (size_t)kt * B_SLAB + wordB(mA, kpl)] = w;
    }
    if (threadIdx.x == 0) {
        g_hn2[t] = ss * inv * inv;
        g_maxQ[t] = -3.0e38f;
    }
}

// ---------------- kernel 1b: pack h^T (B k-major, hi+lo) for g-GEMM --------
__global__ void k_packT() {
    __shared__ float sm[32][129];
    int jb = blockIdx.x;      // d-block (128 wide)
    int kt = blockIdx.y;      // t-chunk (32 tall)
    int tid = threadIdx.x;
#pragma unroll
    for (int it = 0; it < 16; it++) {
        int e = tid + it * 256;
        int tl = e >> 7, dl = e & 127;
        sm[tl][dl] = g_h[(size_t)(kt * 32 + tl) * DD + jb * 128 + dl];
    }
    __syncthreads();
    size_t base = ((size_t)jb * NKT_T + kt) * B_SLAB;
#pragma unroll
    for (int it = 0; it < 8; it++) {
        int w = tid + it * 256;
        int grp = w >> 6, rem = w & 63;
        int lane = rem >> 1, j = rem & 1;
        int n = (grp >> 1) * 8 + (lane >> 2);
        int kp = (grp & 1) * 8 + j * 4 + (lane & 3);
        float h0, l0, h1, l1;
        bsplit(sm[2 * kp][n], h0, l0);
        bsplit(sm[2 * kp + 1][n], h1, l1);
        T_hTh[base + w] = pk(h0, h1);
        T_hTl[base + w] = pk(l0, l1);
    }
}

__global__ void k_tables() {
    int i = blockIdx.x * 256 + threadIdx.x;
    if (i < TT)
        g_invden[i] = 1.0f / (sqrtf((float)DD) * expf(0.1f * (float)i) + 1e-8f);
}

// ---------------- kernel 2: sim = h h^T (1xBF16, BK=64, cp.async ring) -----
__global__ void __launch_bounds__(256, 2) k_sim() {
    extern __shared__ unsigned dsm[];
    uint32_t sb = smem_to_u32(dsm);
    int tid = threadIdx.x, lane = tid & 31, warp = tid >> 5;
    int wm = warp >> 2, wn = warp & 3, gr = lane >> 2, gc = lane & 3;
    int ib, jb;
    triDecode(blockIdx.x, ib, jb);
    int rowA = ib * 128, rowB = jb * 128;

    float acc[4][4][4];
    ACC_INIT(acc)

    const uint4* A4 = (const uint4*)(T_hA + ((size_t)ib * NKT_FULL) * A_SLAB);
    const uint4* B4 = (const uint4*)(T_hB + ((size_t)jb * NKT_FULL) * B_SLAB);

    auto issue = [&](int k2, int buf) {
        uint32_t s = sb + (unsigned)buf * (STAGE1 * 4);
        const uint4* As = A4 + (size_t)k2 * 1024;
        const uint4* Bs = B4 + (size_t)k2 * 1024;
#pragma unroll
        for (int it = 0; it < 4; it++) {
            cpa16(s + (tid + it * 256) * 16, As + tid + it * 256);
            cpa16(s + 16384 + (tid + it * 256) * 16, Bs + tid + it * 256);
        }
    };

    issue(0, 0); CP_COMMIT();
    issue(1, 1); CP_COMMIT();

    for (int k2 = 0; k2 < NKT2; k2++) {
        CP_WAIT1();
        __syncthreads();
        if (k2 + 2 < NKT2) issue(k2 + 2, (k2 + 2) % 3);
        CP_COMMIT();
        const unsigned* S = dsm + (k2 % 3) * STAGE1;
        mma_part1(S, S + 4096, acc, wm, wn, lane);
        mma_part1(S + 2048, S + 6144, acc, wm, wn, lane);
    }

#pragma unroll
    for (int i = 0; i < 4; i++) {
        int t = rowA + (wm * 4 + i) * 16 + gr;
#pragma unroll
        for (int j = 0; j < 4; j++) {
            int s = rowB + (wn * 4 + j) * 8 + gc * 2;
            *(float2*)&g_sim[(size_t)t * TT + s]       = make_float2(acc[i][j][0], acc[i][j][1]);
            *(float2*)&g_sim[(size_t)(t + 8) * TT + s] = make_float2(acc[i][j][2], acc[i][j][3]);
        }
    }
}

// ---------------- kernel 3: softmax (smem row) -> packed alpha fragments ---
__global__ void k_softmax() {
    extern __shared__ float srow[];
    __shared__ float sh[32];
    int t = blockIdx.x;
    const float* row = g_sim + (size_t)t * TT;
    int n = t + 1;
    float lmax = -3.0e38f;
    for (int s = threadIdx.x; s < n; s += blockDim.x) {
        float l = row[s] * g_invden[t - s];
        srow[s] = l;
        lmax = fmaxf(lmax, l);
    }
    lmax = blockReduceMax(lmax, sh);
    float lsum = 0.f;
    for (int s = threadIdx.x; s < n; s += blockDim.x) {
        float e = __expf(srow[s] - lmax);
        srow[s] = e;
        lsum += e;
    }
    lsum = blockReduceSum(lsum, sh);
    float inv = 1.0f / lsum;

    int ib = t >> 7, m = t & 127;
    size_t base = ((size_t)ib * NKT_T) * A_SLAB;
    int npairs = (ib + 1) * 64;
    for (int sp = threadIdx.x; sp < npairs; sp += blockDim.x) {
        int s0 = 2 * sp, s1 = s0 + 1;
        float v0 = (s0 <= t) ? srow[s0] * inv : 0.f;
        float v1 = (s1 <= t) ? srow[s1] * inv : 0.f;
        float h0, l0, h1, l1;
        bsplit(v0, h0, l0);
        bsplit(v1, h1, l1);
        size_t idx = base + (size_t)(sp >> 4) * A_SLAB + wordA(m, sp & 15);
        T_aAh[idx] = pk(h0, h1);
        T_aAl[idx] = pk(l0, l1);
    }
}

// ---------------- kernel 4: g = alpha @ h (3xBF16, split-K=2) --------------
// grid (NDB, 2*NBLK): y encodes (ib, z) with BOTH halves of long blocks first
__global__ void __launch_bounds__(256, 2) k_g() {
    extern __shared__ unsigned dsm[];
    uint32_t sb = smem_to_u32(dsm);
    int tid = threadIdx.x, lane = tid & 31, warp = tid >> 5;
    int wm = warp >> 2, wn = warp & 3, gr = lane >> 2, gc = lane & 3;
    int jbD = blockIdx.x;
    int ib = (NBLK - 1) - (blockIdx.y >> 1);  // long blocks first
    int z = blockIdx.y & 1;                   // k-split half (interleaved)
    int rowA = ib * 128, colB = jbD * 128;
    int nkt = (ib + 1) * 4;
    int beg = z ? nkt / 2 : 0;
    int end = z ? nkt : nkt / 2;

    float acc[4][4][4];
    ACC_INIT(acc)

    const uint4* Ah4 = (const uint4*)(T_aAh + ((size_t)ib * NKT_T) * A_SLAB);
    const uint4* Al4 = (const uint4*)(T_aAl + ((size_t)ib * NKT_T) * A_SLAB);
    const uint4* Bh4 = (const uint4*)(T_hTh + ((size_t)jbD * NKT_T) * B_SLAB);
    const uint4* Bl4 = (const uint4*)(T_hTl + ((size_t)jbD * NKT_T) * B_SLAB);

    // stage layout: [Ah(2048) Al(2048) Bh(2048) Bl(2048)] words
    auto issue = [&](int kt, int buf) {
        uint32_t s = sb + (unsigned)buf * (STAGE3 * 4);
        size_t o = (size_t)kt * 512;
#pragma unroll
        for (int it = 0; it < 2; it++) {
            cpa16(s + (tid + it * 256) * 16, Ah4 + o + tid + it * 256);
            cpa16(s + 8192 + (tid + it * 256) * 16, Al4 + o + tid + it * 256);
            cpa16(s + 16384 + (tid + it * 256) * 16, Bh4 + o + tid + it * 256);
            cpa16(s + 24576 + (tid + it * 256) * 16, Bl4 + o + tid + it * 256);
        }
    };

    issue(beg, 0); CP_COMMIT();
    issue(beg + 1, 1); CP_COMMIT();       // end-beg >= 2 always

    int cnt = end - beg;
    for (int i = 0; i < cnt; i++) {
        CP_WAIT1();
        __syncthreads();
        if (i + 2 < cnt) issue(beg + i + 2, (i + 2) % 3);
        CP_COMMIT();
        const unsigned* S = dsm + (i % 3) * STAGE3;
        mma_part3(S, S + 4096, acc, wm, wn, lane);
    }

    float* dst = z ? g_part1 : g_part0;
#pragma unroll
    for (int i = 0; i < 4; i++) {
#pragma unroll
        for (int half = 0; half < 2; half++) {
            int t = rowA + (wm * 4 + i) * 16 + gr + half * 8;
#pragma unroll
            for (int j = 0; j < 4; j++) {
                int d = colB + (wn * 4 + j) * 8 + gc * 2;
                *(float2*)&dst[(size_t)t * DD + d] =
                    make_float2(acc[i][j][half * 2], acc[i][j][half * 2 + 1]);
            }
        }
    }
}

// ---------------- kernel 4b: g = part0 + part1; write fp32 + packed frags --
__global__ void k_gred() {
    int t = blockIdx.x;
    int m = t & 127;
    size_t roff = (size_t)t * DD;
    size_t gbase = ((size_t)(t >> 7) * NKT_FULL) * A_SLAB;
    for (int dp = threadIdx.x; dp < DD / 2; dp += blockDim.x) {
        int d = dp * 2;
        float2 a = *(const float2*)&g_part0[roff + d];
        float2 b = *(const float2*)&g_part1[roff + d];
        float v0 = a.x + b.x, v1 = a.y + b.y;
        *(float2*)&g_g[roff + d] = make_float2(v0, v1);
        T_gA[gbase + (size_t)(dp >> 4) * A_SLAB + wordA(m, dp & 15)] = pk(v0, v1);
    }
}

// ---------------- kernel 5: cross = g h^T + fused causal max (1xBF16) ------
__global__ void __launch_bounds__(256, 2) k_cross() {
    extern __shared__ unsigned dsm[];
    uint32_t sb = smem_to_u32(dsm);
    int tid = threadIdx.x, lane = tid & 31, warp = tid >> 5;
    int wm = warp >> 2, wn = warp & 3, gr = lane >> 2, gc = lane & 3;
    int ib, jb;
    triDecode(blockIdx.x, ib, jb);
    int rowA = ib * 128, rowB = jb * 128;

    float acc[4][4][4];
    ACC_INIT(acc)

    const uint4* A4 = (const uint4*)(T_gA + ((size_t)ib * NKT_FULL) * A_SLAB);
    const uint4* B4 = (const uint4*)(T_hB + ((size_t)jb * NKT_FULL) * B_SLAB);

    auto issue = [&](int k2, int buf) {
        uint32_t s = sb + (unsigned)buf * (STAGE1 * 4);
        const uint4* As = A4 + (size_t)k2 * 1024;
        const uint4* Bs = B4 + (size_t)k2 * 1024;
#pragma unroll
        for (int it = 0; it < 4; it++) {
            cpa16(s + (tid + it * 256) * 16, As + tid + it * 256);
            cpa16(s + 16384 + (tid + it * 256) * 16, Bs + tid + it * 256);
        }
    };

    issue(0, 0); CP_COMMIT();
    issue(1, 1); CP_COMMIT();

    for (int k2 = 0; k2 < NKT2; k2++) {
        CP_WAIT1();
        __syncthreads();
        if (k2 + 2 < NKT2) issue(k2 + 2, (k2 + 2) % 3);
        CP_COMMIT();
        const unsigned* S = dsm + (k2 % 3) * STAGE1;
        mma_part1(S, S + 4096, acc, wm, wn, lane);
        mma_part1(S + 2048, S + 6144, acc, wm, wn, lane);
    }

    // epilogue: maxQ[t] = max_{s<=t}(hn2[s] - 2*cross[t,s])
    float hn[4][2];
#pragma unroll
    for (int j = 0; j < 4; j++)
#pragma unroll
        for (int e = 0; e < 2; e++)
            hn[j][e] = g_hn2[rowB + (wn * 4 + j) * 8 + gc * 2 + e];

    __syncthreads();
    float* red = (float*)dsm;
#pragma unroll
    for (int i = 0; i < 4; i++) {
        int rloc = (wm * 4 + i) * 16 + gr;
        int t0 = rowA + rloc;
        float m0 = -3.0e38f, m1 = -3.0e38f;
#pragma unroll
        for (int j = 0; j < 4; j++)
#pragma unroll
            for (int e = 0; e < 2; e++) {
                int s = rowB + (wn * 4 + j) * 8 + gc * 2 + e;
                float q0 = hn[j][e] - 2.0f * acc[i][j][e];
                float q1 = hn[j][e] - 2.0f * acc[i][j][2 + e];
                if (s <= t0)     m0 = fmaxf(m0, q0);
                if (s <= t0 + 8) m1 = fmaxf(m1, q1);
            }
#pragma unroll
        for (int o = 1; o < 4; o <<= 1) {
            m0 = fmaxf(m0, __shfl_xor_sync(0xffffffffu, m0, o));
            m1 = fmaxf(m1, __shfl_xor_sync(0xffffffffu, m1, o));
        }
        if (gc == 0) {
            red[rloc * 4 + wn]       = m0;
            red[(rloc + 8) * 4 + wn] = m1;
        }
    }
    __syncthreads();
    if (tid < 128) {
        float m = fmaxf(fmaxf(red[tid * 4], red[tid * 4 + 1]),
                        fmaxf(red[tid * 4 + 2], red[tid * 4 + 3]));
        if (m > -2.0e38f) atomicMaxF(&g_maxQ[rowA + tid], m);
    }
}

// ---------------- kernel 6: final elementwise ------------------------------
__global__ void k_final(const float* __restrict__ m_t, const float* __restrict__ c_t,
                        const float* __restrict__ d_t, const float* __restrict__ mu,
                        float* __restrict__ out) {
    __shared__ float sh[32];
    int t = blockIdx.x;
    const float* hr = g_h + (size_t)t * DD;
    const float* gr = g_g + (size_t)t * DD;
    float dd = 0.f, gn2 = 0.f;
    for (int i = threadIdx.x; i < DD; i += blockDim.x) {
        float hv = hr[i], gv = gr[i];
        float df = hv - gv;
        dd += df * df;
        gn2 += gv * gv;
    }
    dd = blockReduceSum(dd, sh);
    gn2 = blockReduceSum(gn2, sh);
    if (threadIdx.x == 0) {
        float dist = sqrtf(fmaxf(dd, 1e-24f));
        float dmax = sqrtf(fmaxf(gn2 + g_maxQ[t], 1e-24f));
        if (dmax < 1e-6f) dmax = 1.0f;
        float ratio = dist / (dmax + 1e-8f);
        float stab = 1.0f - 0.3f * c_t[t] + 0.2f * d_t[t];
        float xi = 1.0f - mu[0] * m_t[t];
        float v = ratio * stab * xi;
        out[t] = fminf(fmaxf(v, 0.0f), 1.0f);
    }
}

// ---------------- launch ----------------------------------------------------
extern "C" void kernel_launch(void* const* d_in, const int* in_sizes, int n_in,
                              void* d_out, int out_size) {
    const float* x   = (const float*)d_in[0];
    const float* m_t = (const float*)d_in[1];
    const float* c_t = (const float*)d_in[2];
    const float* d_t = (const float*)d_in[3];
    const float* mu  = (const float*)d_in[4];
    float* out = (float*)d_out;

    cudaFuncSetAttribute(k_sim,     cudaFuncAttributeMaxDynamicSharedMemorySize, DSMEM1);
    cudaFuncSetAttribute(k_g,       cudaFuncAttributeMaxDynamicSharedMemorySize, DSMEM3);
    cudaFuncSetAttribute(k_cross,   cudaFuncAttributeMaxDynamicSharedMemorySize, DSMEM1);
    cudaFuncSetAttribute(k_softmax, cudaFuncAttributeMaxDynamicSharedMemorySize, DSMEM_SM);

    k_normalize<<<TT, 256>>>(x);
    k_packT<<<dim3(NDB, NKT_T), 256>>>();
    k_tables<<<TT / 256, 256>>>();
    k_sim<<<NPAIR, 256, DSMEM1>>>();
    k_softmax<<<TT, 256, DSMEM_SM>>>();
    k_g<<<dim3(NDB, NBLK * 2), 256, DSMEM3>>>();
    k_gred<<<TT, 256>>>();
    k_cross<<<NPAIR, 256, DSMEM1>>>();
    k_final<<<TT, 256>>>(m_t, c_t, d_t, mu, out);
}